// round 4
// baseline (speedup 1.0000x reference)
#include <cuda_runtime.h>
#include <cstdint>

#define PATH_NUM 64

__device__ __forceinline__ bool better(float va, int ia, float vb, int ib) {
    // strictly greater value wins; on tie, lower index wins (matches jax top_k)
    return (va > vb) || (va == vb && ia < ib);
}

__global__ void __launch_bounds__(256)
topk2_onehot_kernel(const float* __restrict__ score,
                    float* __restrict__ out,
                    int n_rows) {
    int gtid = blockIdx.x * blockDim.x + threadIdx.x;
    int row  = gtid >> 5;
    if (row >= n_rows) return;
    int lane = threadIdx.x & 31;

    // Coalesced float2 load: lane i handles columns 2i and 2i+1
    const float2 s =
        reinterpret_cast<const float2*>(score + (size_t)row * PATH_NUM)[lane];
    int i0 = lane * 2, i1 = lane * 2 + 1;

    // Local sorted top-2 (tie -> lower index, i.e. i0)
    float a_v, b_v; int a_i, b_i;
    if (s.x >= s.y) { a_v = s.x; a_i = i0; b_v = s.y; b_i = i1; }
    else            { a_v = s.y; a_i = i1; b_v = s.x; b_i = i0; }

    // Butterfly merge of sorted top-2 pairs across the warp
    #pragma unroll
    for (int off = 16; off > 0; off >>= 1) {
        float oa_v = __shfl_xor_sync(0xFFFFFFFFu, a_v, off);
        int   oa_i = __shfl_xor_sync(0xFFFFFFFFu, a_i, off);
        float ob_v = __shfl_xor_sync(0xFFFFFFFFu, b_v, off);
        int   ob_i = __shfl_xor_sync(0xFFFFFFFFu, b_i, off);

        float t_v, u_v; int t_i, u_i;
        if (better(a_v, a_i, oa_v, oa_i)) {
            // top1 = a; second = better of {b, oa} (oa >= ob)
            t_v = a_v; t_i = a_i;
            if (better(b_v, b_i, oa_v, oa_i)) { u_v = b_v; u_i = b_i; }
            else                              { u_v = oa_v; u_i = oa_i; }
        } else {
            // top1 = oa; second = better of {a, ob} (a >= b)
            t_v = oa_v; t_i = oa_i;
            if (better(a_v, a_i, ob_v, ob_i)) { u_v = a_v; u_i = a_i; }
            else                              { u_v = ob_v; u_i = ob_i; }
        }
        a_v = t_v; a_i = t_i; b_v = u_v; b_i = u_i;
    }
    // All lanes now agree on (a_i, b_i) = top-2 column indices.

    // Coalesced float2 store: lane i writes columns 2i, 2i+1 (float32 output)
    float2 o;
    o.x = (i0 == a_i || i0 == b_i) ? 1.0f : 0.0f;
    o.y = (i1 == a_i || i1 == b_i) ? 1.0f : 0.0f;
    reinterpret_cast<float2*>(out + (size_t)row * PATH_NUM)[lane] = o;
}

extern "C" void kernel_launch(void* const* d_in, const int* in_sizes, int n_in,
                              void* d_out, int out_size) {
    const float* score = (const float*)d_in[0];
    float*       out   = (float*)d_out;

    int n_rows_in  = in_sizes[0] / PATH_NUM;
    int n_rows_out = out_size / PATH_NUM;
    int n_rows = n_rows_in < n_rows_out ? n_rows_in : n_rows_out;

    // one warp per row, 8 warps (256 threads) per block
    int blocks = (n_rows + 7) / 8;
    topk2_onehot_kernel<<<blocks, 256>>>(score, out, n_rows);
}

// round 6
// speedup vs baseline: 1.6893x; 1.6893x over previous
#include <cuda_runtime.h>
#include <cstdint>

#define PATH_NUM 64

// Order-preserving float->uint mapping (no NaNs in input):
// negative: flip all bits; non-negative: set sign bit.
__device__ __forceinline__ unsigned f2u_ord(float f) {
    unsigned b = __float_as_uint(f);
    return b ^ (((int)b >> 31) | 0x80000000u);
}

__global__ void __launch_bounds__(256)
topk2_onehot_kernel(const float* __restrict__ score,
                    float* __restrict__ out,
                    int n_rows) {
    int gtid = blockIdx.x * blockDim.x + threadIdx.x;
    int row  = gtid >> 5;
    if (row >= n_rows) return;
    int lane = threadIdx.x & 31;

    // Coalesced streaming float2 load: lane i handles columns 2i, 2i+1
    const float2 s =
        __ldcs(reinterpret_cast<const float2*>(score + (size_t)row * PATH_NUM) + lane);
    int i0 = lane * 2, i1 = i0 + 1;

    unsigned ux = f2u_ord(s.x);
    unsigned uy = f2u_ord(s.y);

    // ---- top-1 ----
    unsigned lmax = ux > uy ? ux : uy;
    unsigned m1 = __reduce_max_sync(0xFFFFFFFFu, lmax);
    unsigned own1 = __ballot_sync(0xFFFFFFFFu, lmax == m1);
    int src1 = __ffs(own1) - 1;                 // lowest lane => lowest column
    int myidx1 = (ux == m1) ? i0 : i1;          // within lane: lower column on tie
    int idx1 = __shfl_sync(0xFFFFFFFFu, myidx1, src1);

    // ---- top-2: owner lane swaps in its other element ----
    bool iown = (lane == src1);
    unsigned cand = iown ? ((idx1 == i0) ? uy : ux) : lmax;
    unsigned m2 = __reduce_max_sync(0xFFFFFFFFu, cand);
    bool cx = (ux == m2) && (i0 != idx1);
    bool cy = (uy == m2) && (i1 != idx1);
    unsigned own2 = __ballot_sync(0xFFFFFFFFu, cx || cy);
    int src2 = __ffs(own2) - 1;
    int myidx2 = cx ? i0 : i1;                  // prefer lower column in-lane
    int idx2 = __shfl_sync(0xFFFFFFFFu, myidx2, src2);

    // Coalesced streaming float2 store (k-hot mask, float32)
    float2 o;
    o.x = (i0 == idx1 || i0 == idx2) ? 1.0f : 0.0f;
    o.y = (i1 == idx1 || i1 == idx2) ? 1.0f : 0.0f;
    __stcs(reinterpret_cast<float2*>(out + (size_t)row * PATH_NUM) + lane, o);
}

extern "C" void kernel_launch(void* const* d_in, const int* in_sizes, int n_in,
                              void* d_out, int out_size) {
    const float* score = (const float*)d_in[0];
    float*       out   = (float*)d_out;

    int n_rows_in  = in_sizes[0] / PATH_NUM;
    int n_rows_out = out_size / PATH_NUM;
    int n_rows = n_rows_in < n_rows_out ? n_rows_in : n_rows_out;

    // one warp per row, 8 warps (256 threads) per block
    int blocks = (n_rows + 7) / 8;
    topk2_onehot_kernel<<<blocks, 256>>>(score, out, n_rows);
}

// round 7
// speedup vs baseline: 2.6529x; 1.5704x over previous
#include <cuda_runtime.h>
#include <cstdint>

#define PATH_NUM 64

// Merge two sorted top-2 value pairs (h>=l) -> exact top-2 of the union,
// duplicate-correct (order statistics with multiplicity). 4 ops, no selects.
__device__ __forceinline__ void merge2(float& h, float& l, float h2, float l2) {
    float hi = fmaxf(h, h2);
    float lo = fmaxf(fminf(h, h2), fmaxf(l, l2));
    h = hi; l = lo;
}

__device__ __forceinline__ void top2_of4(float4 v, float& h, float& l) {
    float h1 = fmaxf(v.x, v.y), l1 = fminf(v.x, v.y);
    float h2 = fmaxf(v.z, v.w), l2 = fminf(v.z, v.w);
    h = fmaxf(h1, h2);
    l = fmaxf(fminf(h1, h2), fmaxf(l1, l2));
}

__global__ void __launch_bounds__(256)
topk2_onehot_kernel(const float* __restrict__ score,
                    float* __restrict__ out,
                    int n_rows) {
    const unsigned FULL = 0xFFFFFFFFu;
    int lane    = threadIdx.x & 31;
    int warp_id = blockIdx.x * (blockDim.x >> 5) + (threadIdx.x >> 5);
    int sub     = lane & 3;                 // position within 4-lane row group
    int row     = warp_id * 8 + (lane >> 2);
    bool valid  = row < n_rows;
    int rowc    = valid ? row : (n_rows - 1);   // clamp so all 32 lanes stay converged

    // Lane handles columns {sub*4 + j*16 + p}: each 4-lane group covers
    // 64 contiguous bytes per load -> fully coalesced sectors.
    const float4* src = reinterpret_cast<const float4*>(score) + (size_t)rowc * 16;
    float4 a0 = __ldcs(src + sub);
    float4 a1 = __ldcs(src + sub + 4);
    float4 a2 = __ldcs(src + sub + 8);
    float4 a3 = __ldcs(src + sub + 12);

    // Local top-2 values over the lane's 16 elements
    float h, l, th, tl;
    top2_of4(a0, h, l);
    top2_of4(a1, th, tl); merge2(h, l, th, tl);
    top2_of4(a2, th, tl); merge2(h, l, th, tl);
    top2_of4(a3, th, tl); merge2(h, l, th, tl);

    // 4-lane group merge (xor-1, xor-2 are group-closed patterns)
    #pragma unroll
    for (int off = 1; off <= 2; off <<= 1) {
        float oh = __shfl_xor_sync(FULL, h, off);
        float ol = __shfl_xor_sync(FULL, l, off);
        merge2(h, l, oh, ol);
    }
    const float m2 = l;   // exact 2nd order statistic of the row

    float vv[16] = {a0.x, a0.y, a0.z, a0.w,  a1.x, a1.y, a1.z, a1.w,
                    a2.x, a2.y, a2.z, a2.w,  a3.x, a3.y, a3.z, a3.w};

    // Fast path: hot = (v >= m2); count across group to detect boundary ties
    unsigned hotbits = 0;
    int c = 0;
    #pragma unroll
    for (int e = 0; e < 16; e++) {
        bool hot = vv[e] >= m2;
        hotbits |= (unsigned)hot << e;
        c += hot;
    }
    c += __shfl_xor_sync(FULL, c, 1);
    c += __shfl_xor_sync(FULL, c, 2);

    if (c != 2) {
        // Rare exact path: duplicates at the top-2 boundary. Keep all v > m2,
        // then the lowest-index elements equal to m2 (jax top_k stability).
        unsigned gmask = 0xFu << (lane & ~3);   // this group's converged lanes
        int gt = 0;
        unsigned eqflags = 0;
        #pragma unroll
        for (int e = 0; e < 16; e++) {
            gt += (vv[e] > m2);
            if (vv[e] == m2) eqflags |= 1u << e;
        }
        // pack per-j (j = column/16 stripe) eq counts, 4 bits each, + gt at 16
        unsigned pack = (unsigned)gt << 16;
        #pragma unroll
        for (int j = 0; j < 4; j++)
            pack |= (unsigned)__popc((eqflags >> (4 * j)) & 0xFu) << (4 * j);
        int base = lane & ~3;
        unsigned pk0 = __shfl_sync(gmask, pack, base + 0);
        unsigned pk1 = __shfl_sync(gmask, pack, base + 1);
        unsigned pk2 = __shfl_sync(gmask, pack, base + 2);
        unsigned pk3 = __shfl_sync(gmask, pack, base + 3);
        unsigned pk[4] = {pk0, pk1, pk2, pk3};
        int gt_all = (int)((pk0 >> 16) + (pk1 >> 16) + (pk2 >> 16) + (pk3 >> 16));

        hotbits = 0;
        // global column order is (j, sub, p): col = j*16 + sub*4 + p
        int eq_before_j = 0;   // eq count in stripes j' < j (all subs)
        #pragma unroll
        for (int j = 0; j < 4; j++) {
            int eq_lower_sub = 0;
            #pragma unroll
            for (int s = 0; s < 4; s++)
                if (s < sub) eq_lower_sub += (int)((pk[s] >> (4 * j)) & 0xFu);
            #pragma unroll
            for (int p = 0; p < 4; p++) {
                int e = j * 4 + p;
                bool isgt = vv[e] > m2;
                bool iseq = (eqflags >> e) & 1u;
                int eq_in_lane_before =
                    __popc(eqflags & ((1u << e) - 1u) & (0xFu << (4 * j)));
                int rank_eq = eq_before_j + eq_lower_sub + eq_in_lane_before;
                bool hot = isgt || (iseq && (gt_all + rank_eq) < 2);
                hotbits |= (unsigned)hot << e;
            }
            int eq_j_all = 0;
            #pragma unroll
            for (int s = 0; s < 4; s++)
                eq_j_all += (int)((pk[s] >> (4 * j)) & 0xFu);
            eq_before_j += eq_j_all;
        }
    }

    if (valid) {
        float4* dst = reinterpret_cast<float4*>(out) + (size_t)rowc * 16;
        #pragma unroll
        for (int j = 0; j < 4; j++) {
            float4 o;
            o.x = (hotbits >> (j * 4 + 0)) & 1u ? 1.0f : 0.0f;
            o.y = (hotbits >> (j * 4 + 1)) & 1u ? 1.0f : 0.0f;
            o.z = (hotbits >> (j * 4 + 2)) & 1u ? 1.0f : 0.0f;
            o.w = (hotbits >> (j * 4 + 3)) & 1u ? 1.0f : 0.0f;
            __stcs(dst + sub + j * 4, o);
        }
    }
}

extern "C" void kernel_launch(void* const* d_in, const int* in_sizes, int n_in,
                              void* d_out, int out_size) {
    const float* score = (const float*)d_in[0];
    float*       out   = (float*)d_out;

    int n_rows_in  = in_sizes[0] / PATH_NUM;
    int n_rows_out = out_size / PATH_NUM;
    int n_rows = n_rows_in < n_rows_out ? n_rows_in : n_rows_out;

    int warps  = (n_rows + 7) / 8;          // 8 rows per warp
    int blocks = (warps * 32 + 255) / 256;
    topk2_onehot_kernel<<<blocks, 256>>>(score, out, n_rows);
}